// round 5
// baseline (speedup 1.0000x reference)
#include <cuda_runtime.h>
#include <cuda_bf16.h>
#include <cstdint>

#define NPG   100
#define DEG   16
#define BLK   256
#define NGRAPH 512
#define NNODES (NGRAPH * NPG)
#define SP    120          // padded s-stride in bf16 halves (conflict-free)
#define SP32  60           // same stride in uint32 (bf16x2)

// P^T staged between kernels: [graph][d=100][s-stride 120] bf16 hi/lo
__device__ __nv_bfloat16 PT_hi_g[(size_t)NGRAPH * NPG * SP];
__device__ __nv_bfloat16 PT_lo_g[(size_t)NGRAPH * NPG * SP];

// ---------------- helpers ----------------
__device__ __forceinline__ uint32_t cvt_tf32(float x) {
    uint32_t r;
    asm("cvt.rna.tf32.f32 %0, %1;" : "=r"(r) : "f"(x));
    return r;
}
__device__ __forceinline__ void mma_tf32(float* acc, const uint32_t* a,
                                         uint32_t b0, uint32_t b1) {
    asm volatile("mma.sync.aligned.m16n8k8.row.col.f32.tf32.tf32.f32 "
                 "{%0,%1,%2,%3}, {%4,%5,%6,%7}, {%8,%9}, {%0,%1,%2,%3};"
                 : "+f"(acc[0]), "+f"(acc[1]), "+f"(acc[2]), "+f"(acc[3])
                 : "r"(a[0]), "r"(a[1]), "r"(a[2]), "r"(a[3]),
                   "r"(b0), "r"(b1));
}
__device__ __forceinline__ void mma_bf16(float* c, const uint32_t* a,
                                         uint32_t b0, uint32_t b1) {
    asm volatile("mma.sync.aligned.m16n8k16.row.col.f32.bf16.bf16.f32 "
                 "{%0,%1,%2,%3}, {%4,%5,%6,%7}, {%8,%9}, {%0,%1,%2,%3};"
                 : "+f"(c[0]), "+f"(c[1]), "+f"(c[2]), "+f"(c[3])
                 : "r"(a[0]), "r"(a[1]), "r"(a[2]), "r"(a[3]),
                   "r"(b0), "r"(b1));
}
// split (x,y) into packed bf16x2 hi and lo
__device__ __forceinline__ void split2(float x, float y,
                                       uint32_t& hi, uint32_t& lo) {
    __nv_bfloat16 hx = __float2bfloat16(x), hy = __float2bfloat16(y);
    __nv_bfloat16 lx = __float2bfloat16(x - __bfloat162float(hx));
    __nv_bfloat16 ly = __float2bfloat16(y - __bfloat162float(hy));
    hi = (uint32_t)*(uint16_t*)&hx | ((uint32_t)*(uint16_t*)&hy << 16);
    lo = (uint32_t)*(uint16_t*)&lx | ((uint32_t)*(uint16_t*)&ly << 16);
}

// ====================== kernel 1: tf32 GEMM, bf16-split transposed epilogue ======================
#define KP 108
#define NPAD 104
#define K1_SMEM (2 * NPAD * KP * sizeof(float))

__device__ __forceinline__ void emit_pt(float v, int node, int d) {
    int gr = node / 100;
    int s  = node - gr * 100;
    size_t idx = ((size_t)gr * 100 + d) * SP + s;
    __nv_bfloat16 h = __float2bfloat16(v);
    PT_hi_g[idx] = h;
    PT_lo_g[idx] = __float2bfloat16(v - __bfloat162float(h));
}

__global__ __launch_bounds__(BLK, 2)
void gemm1_kernel(const float* __restrict__ feat, const float* __restrict__ W1)
{
    extern __shared__ uint32_t sm1[];
    uint32_t* Bhi = sm1;
    uint32_t* Blo = sm1 + NPAD * KP;

    const int tid  = threadIdx.x;
    const int warp = tid >> 5;
    const int lane = tid & 31;
    const int qg   = lane >> 2;
    const int tig  = lane & 3;

    for (int i = tid; i < 2 * NPAD * KP; i += BLK) sm1[i] = 0u;
    __syncthreads();

    {
        const float4* gw = (const float4*)W1;
        for (int i = tid; i < 100 * 100 / 4; i += BLK) {
            float4 v = gw[i];
            int row = (i * 4) / 100, col = (i * 4) % 100;
            uint32_t* dh = Bhi + row * KP + col;
            uint32_t* dl = Blo + row * KP + col;
            float x[4] = { v.x, v.y, v.z, v.w };
            #pragma unroll
            for (int q = 0; q < 4; q++) {
                uint32_t h = cvt_tf32(x[q]);
                dh[q] = h;
                dl[q] = cvt_tf32(x[q] - __uint_as_float(h));
            }
        }
    }
    __syncthreads();

    const int mbase = blockIdx.x * 128 + warp * 16;
    const float* arow0 = feat + (size_t)(mbase + qg) * 100;
    const float* arow1 = feat + (size_t)(mbase + 8 + qg) * 100;

    float acc[13][4];
    #pragma unroll
    for (int nt = 0; nt < 13; nt++)
        #pragma unroll
        for (int q = 0; q < 4; q++) acc[nt][q] = 0.f;

    #pragma unroll 1
    for (int kt = 0; kt < 13; kt++) {
        const int k0 = kt * 8;
        const int kA = k0 + tig;
        const int kB = k0 + tig + 4;
        float a0f = (kA < 100) ? __ldg(arow0 + kA) : 0.f;
        float a1f = (kA < 100) ? __ldg(arow1 + kA) : 0.f;
        float a2f = (kB < 100) ? __ldg(arow0 + kB) : 0.f;
        float a3f = (kB < 100) ? __ldg(arow1 + kB) : 0.f;
        uint32_t ah[4], al[4];
        ah[0] = cvt_tf32(a0f); al[0] = cvt_tf32(a0f - __uint_as_float(ah[0]));
        ah[1] = cvt_tf32(a1f); al[1] = cvt_tf32(a1f - __uint_as_float(ah[1]));
        ah[2] = cvt_tf32(a2f); al[2] = cvt_tf32(a2f - __uint_as_float(ah[2]));
        ah[3] = cvt_tf32(a3f); al[3] = cvt_tf32(a3f - __uint_as_float(ah[3]));

        const uint32_t* bh = Bhi + qg * KP + k0 + tig;
        const uint32_t* bl = Blo + qg * KP + k0 + tig;
        #pragma unroll
        for (int nt = 0; nt < 13; nt++) {
            const int roff = nt * 8 * KP;
            uint32_t bh0 = bh[roff], bh1 = bh[roff + 4];
            uint32_t bl0 = bl[roff], bl1 = bl[roff + 4];
            mma_tf32(acc[nt], ah, bh0, bh1);
            mma_tf32(acc[nt], ah, bl0, bl1);
            mma_tf32(acc[nt], al, bh0, bh1);
        }
    }

    // epilogue: write P^T as bf16 hi/lo   (c0: (r0,col) c1: (r0,col+1) c2/c3: r1)
    const int r0 = mbase + qg, r1 = mbase + 8 + qg;
    #pragma unroll
    for (int nt = 0; nt < 13; nt++) {
        int col = nt * 8 + 2 * tig;
        if (col < 100) {
            emit_pt(acc[nt][0], r0, col);
            emit_pt(acc[nt][1], r0, col + 1);
            emit_pt(acc[nt][2], r1, col);
            emit_pt(acc[nt][3], r1, col + 1);
        }
    }
}

// ====================== kernel 2: bf16 MMA GNN ======================
// smem byte offsets
#define B_PTH 0                      // [112][120] bf16  PT_hi  -> later h1_hi
#define B_PTL 26880                  // [112][120] bf16  PT_lo  -> later h1_lo
#define B_A   53760                  // [112][120] bf16  adjacency/16
#define B_W2H 80640                  // [24][120] bf16
#define B_W2L 86400
#define B_STH 92160                  // [24][120] bf16  sT^T hi
#define B_STL 97920
#define B_B1  103680                 // [100] f32
#define B_B2  104080                 // [20]  f32
#define B_HG  104160                 // [20]  f32
#define B_VEC 104240                 // [32]  f32
#define K2_BYTES 104368

__global__ __launch_bounds__(BLK, 2)
void gnn_rest_kernel(const int*   __restrict__ edge_src,
                     const float* __restrict__ self_feat,
                     const float* __restrict__ x3d,
                     const float* __restrict__ b1,
                     const float* __restrict__ W2, const float* __restrict__ b2,
                     const float* __restrict__ Wv2, const float* __restrict__ Wo2,
                     const float* __restrict__ g2,  const float* __restrict__ be2,
                     const float* __restrict__ Wv3, const float* __restrict__ Wo3,
                     const float* __restrict__ g3,  const float* __restrict__ be3,
                     const float* __restrict__ Wf1, const float* __restrict__ bf1,
                     const float* __restrict__ Wf2, const float* __restrict__ bf2,
                     float* __restrict__ out)
{
    extern __shared__ unsigned char sm[];
    const int g    = blockIdx.x;
    const int tid  = threadIdx.x;
    const int lane = tid & 31;
    const int warp = tid >> 5;
    const int qg   = lane >> 2;     // groupID
    const int tig  = lane & 3;      // thread in group

    // ---- init: zero A/W2/sTT region; load biases ----
    {
        uint2 z = make_uint2(0, 0);
        uint2* p = (uint2*)(sm + B_A);
        for (int i = tid; i < (B_B1 - B_A) / 8; i += BLK) p[i] = z;
    }
    if (tid < 100) ((float*)(sm + B_B1))[tid] = b1[tid];
    if (tid < 20)  ((float*)(sm + B_B2))[tid] = b2[tid];
    if (tid < 20)  ((float*)(sm + B_HG))[tid] = 0.f;

    // ---- load PT hi/lo tiles (zero padding s>=100, rows>=100) ----
    {
        const uint2* gh = (const uint2*)(PT_hi_g + (size_t)g * NPG * SP);
        const uint2* gl = (const uint2*)(PT_lo_g + (size_t)g * NPG * SP);
        uint2* sh = (uint2*)(sm + B_PTH);
        uint2* sl = (uint2*)(sm + B_PTL);
        for (int i = tid; i < 112 * 30; i += BLK) {
            int row = i / 30, j = i % 30;
            uint2 vh = make_uint2(0, 0), vl = make_uint2(0, 0);
            if (row < 100 && j < 25) { vh = gh[row * 30 + j]; vl = gl[row * 30 + j]; }
            sh[i] = vh; sl[i] = vl;
        }
    }
    // ---- W2 -> bf16 hi/lo [o][d] ----
    {
        const float4* gw = (const float4*)W2;
        uint32_t* wh = (uint32_t*)(sm + B_W2H);
        uint32_t* wl = (uint32_t*)(sm + B_W2L);
        for (int i = tid; i < 500; i += BLK) {
            float4 v = gw[i];
            int row = (i * 4) / 100, col = (i * 4) % 100;
            uint32_t h0, l0, h1, l1;
            split2(v.x, v.y, h0, l0);
            split2(v.z, v.w, h1, l1);
            wh[row * SP32 + col / 2]     = h0;
            wh[row * SP32 + col / 2 + 1] = h1;
            wl[row * SP32 + col / 2]     = l0;
            wl[row * SP32 + col / 2 + 1] = l1;
        }
    }
    __syncthreads();   // zeros of A visible before RMW build

    // ---- build adjacency A[dst][src] += 1/16 (exact in bf16); one thread per dst ----
    if (tid < 100) {
        const int4* es = (const int4*)(edge_src + (size_t)g * NPG * DEG + tid * DEG);
        const int base = g * NPG;
        __nv_bfloat16* arow = (__nv_bfloat16*)(sm + B_A) + tid * SP;
        #pragma unroll
        for (int q = 0; q < 4; q++) {
            int4 e4 = es[q];
            int s0 = e4.x - base, s1 = e4.y - base, s2 = e4.z - base, s3 = e4.w - base;
            arow[s0] = __float2bfloat16(__bfloat162float(arow[s0]) + 0.0625f);
            arow[s1] = __float2bfloat16(__bfloat162float(arow[s1]) + 0.0625f);
            arow[s2] = __float2bfloat16(__bfloat162float(arow[s2]) + 0.0625f);
            arow[s3] = __float2bfloat16(__bfloat162float(arow[s3]) + 0.0625f);
        }
    }
    __syncthreads();   // S0

    // ---- MMA1: h1 = relu(A @ P + b1)  (A exact, P hi/lo: 2 passes) ----
    float c[13][4];
    uint32_t afr[7][4];
    const int m0 = warp * 16;
    const int r0 = m0 + qg, r1 = m0 + 8 + qg;
    if (warp < 7) {
        const uint32_t* A32 = (const uint32_t*)(sm + B_A);
        #pragma unroll
        for (int k = 0; k < 7; k++) {
            int i0 = (m0 + qg) * SP32 + k * 8 + tig;
            int i1 = (m0 + 8 + qg) * SP32 + k * 8 + tig;
            afr[k][0] = A32[i0];     afr[k][1] = A32[i1];
            afr[k][2] = A32[i0 + 4]; afr[k][3] = A32[i1 + 4];
        }
        const uint32_t* PH = (const uint32_t*)(sm + B_PTH);
        const uint32_t* PL = (const uint32_t*)(sm + B_PTL);
        #pragma unroll
        for (int nt = 0; nt < 13; nt++) {
            c[nt][0] = c[nt][1] = c[nt][2] = c[nt][3] = 0.f;
            const int bb = (nt * 8 + qg) * SP32 + tig;
            #pragma unroll
            for (int k = 0; k < 7; k++)
                mma_bf16(c[nt], afr[k], PH[bb + k * 8], PH[bb + k * 8 + 4]);
            #pragma unroll
            for (int k = 0; k < 7; k++)
                mma_bf16(c[nt], afr[k], PL[bb + k * 8], PL[bb + k * 8 + 4]);
        }
    }
    __syncthreads();   // S1: all PT reads done

    // zero h1 regions (overlay PT)
    {
        uint4 z = make_uint4(0, 0, 0, 0);
        uint4* p = (uint4*)sm;
        for (int i = tid; i < 53760 / 16; i += BLK) p[i] = z;
    }
    __syncthreads();   // S2

    if (warp < 7) {
        uint32_t* H1H = (uint32_t*)(sm + B_PTH);
        uint32_t* H1L = (uint32_t*)(sm + B_PTL);
        const float* b1s = (const float*)(sm + B_B1);
        #pragma unroll
        for (int nt = 0; nt < 13; nt++) {
            int col = nt * 8 + 2 * tig;
            if (col < 100) {
                float bx = b1s[col], by = b1s[col + 1];
                if (r0 < 100) {
                    float v0 = fmaxf(c[nt][0] + bx, 0.f);
                    float v1 = fmaxf(c[nt][1] + by, 0.f);
                    uint32_t hi, lo; split2(v0, v1, hi, lo);
                    H1H[r0 * SP32 + col / 2] = hi;
                    H1L[r0 * SP32 + col / 2] = lo;
                }
                if (r1 < 100) {
                    float v0 = fmaxf(c[nt][2] + bx, 0.f);
                    float v1 = fmaxf(c[nt][3] + by, 0.f);
                    uint32_t hi, lo; split2(v0, v1, hi, lo);
                    H1H[r1 * SP32 + col / 2] = hi;
                    H1L[r1 * SP32 + col / 2] = lo;
                }
            }
        }
    }
    __syncthreads();   // S3

    // ---- MMA2: sT = h1 @ W2^T  (hi/lo x hi/lo: 3 passes) -> sT^T bf16 hi/lo ----
    if (warp < 7) {
        const uint32_t* H1H = (const uint32_t*)(sm + B_PTH);
        const uint32_t* H1L = (const uint32_t*)(sm + B_PTL);
        const uint32_t* WH  = (const uint32_t*)(sm + B_W2H);
        const uint32_t* WL  = (const uint32_t*)(sm + B_W2L);
        uint32_t ah[7][4], al[7][4];
        #pragma unroll
        for (int k = 0; k < 7; k++) {
            int i0 = (m0 + qg) * SP32 + k * 8 + tig;
            int i1 = (m0 + 8 + qg) * SP32 + k * 8 + tig;
            ah[k][0] = H1H[i0];     ah[k][1] = H1H[i1];
            ah[k][2] = H1H[i0 + 4]; ah[k][3] = H1H[i1 + 4];
            al[k][0] = H1L[i0];     al[k][1] = H1L[i1];
            al[k][2] = H1L[i0 + 4]; al[k][3] = H1L[i1 + 4];
        }
        float s3[3][4];
        #pragma unroll
        for (int nt = 0; nt < 3; nt++) {
            s3[nt][0] = s3[nt][1] = s3[nt][2] = s3[nt][3] = 0.f;
            const int bb = (nt * 8 + qg) * SP32 + tig;
            #pragma unroll
            for (int k = 0; k < 7; k++) {
                uint32_t bh0 = WH[bb + k * 8], bh1 = WH[bb + k * 8 + 4];
                uint32_t bl0 = WL[bb + k * 8], bl1 = WL[bb + k * 8 + 4];
                mma_bf16(s3[nt], ah[k], bh0, bh1);
                mma_bf16(s3[nt], ah[k], bl0, bl1);
                mma_bf16(s3[nt], al[k], bh0, bh1);
            }
        }
        // epilogue: transposed store sT^T[o][node] bf16 hi/lo
        __nv_bfloat16* STH = (__nv_bfloat16*)(sm + B_STH);
        __nv_bfloat16* STL = (__nv_bfloat16*)(sm + B_STL);
        #pragma unroll
        for (int nt = 0; nt < 3; nt++) {
            int col = nt * 8 + 2 * tig;
            if (col < 20) {
                if (r0 < 100) {
                    __nv_bfloat16 h0 = __float2bfloat16(s3[nt][0]);
                    __nv_bfloat16 h1v = __float2bfloat16(s3[nt][1]);
                    STH[col * SP + r0]       = h0;
                    STL[col * SP + r0]       = __float2bfloat16(s3[nt][0] - __bfloat162float(h0));
                    STH[(col + 1) * SP + r0] = h1v;
                    STL[(col + 1) * SP + r0] = __float2bfloat16(s3[nt][1] - __bfloat162float(h1v));
                }
                if (r1 < 100) {
                    __nv_bfloat16 h0 = __float2bfloat16(s3[nt][2]);
                    __nv_bfloat16 h1v = __float2bfloat16(s3[nt][3]);
                    STH[col * SP + r1]       = h0;
                    STL[col * SP + r1]       = __float2bfloat16(s3[nt][2] - __bfloat162float(h0));
                    STH[(col + 1) * SP + r1] = h1v;
                    STL[(col + 1) * SP + r1] = __float2bfloat16(s3[nt][3] - __bfloat162float(h1v));
                }
            }
        }
    }
    __syncthreads();   // S4

    // ---- MMA3: agg2 = A @ sT (2 passes); h2 = relu(agg2 + b2); hg accum ----
    if (warp < 7) {
        const uint32_t* A32 = (const uint32_t*)(sm + B_A);
        const uint32_t* SH  = (const uint32_t*)(sm + B_STH);
        const uint32_t* SL  = (const uint32_t*)(sm + B_STL);
        float* shg = (float*)(sm + B_HG);
        const float* b2s = (const float*)(sm + B_B2);
        uint32_t a2[7][4];
        #pragma unroll
        for (int k = 0; k < 7; k++) {
            int i0 = (m0 + qg) * SP32 + k * 8 + tig;
            int i1 = (m0 + 8 + qg) * SP32 + k * 8 + tig;
            a2[k][0] = A32[i0];     a2[k][1] = A32[i1];
            a2[k][2] = A32[i0 + 4]; a2[k][3] = A32[i1 + 4];
        }
        #pragma unroll
        for (int nt = 0; nt < 3; nt++) {
            float t[4] = {0.f, 0.f, 0.f, 0.f};
            const int bb = (nt * 8 + qg) * SP32 + tig;
            #pragma unroll
            for (int k = 0; k < 7; k++) {
                mma_bf16(t, a2[k], SH[bb + k * 8], SH[bb + k * 8 + 4]);
                mma_bf16(t, a2[k], SL[bb + k * 8], SL[bb + k * 8 + 4]);
            }
            int col = nt * 8 + 2 * tig;
            if (col < 20) {
                float bx = b2s[col], by = b2s[col + 1];
                float acc0 = (r0 < 100 ? fmaxf(t[0] + bx, 0.f) : 0.f)
                           + (r1 < 100 ? fmaxf(t[2] + bx, 0.f) : 0.f);
                float acc1 = (r0 < 100 ? fmaxf(t[1] + by, 0.f) : 0.f)
                           + (r1 < 100 ? fmaxf(t[3] + by, 0.f) : 0.f);
                atomicAdd(shg + col, acc0);
                atomicAdd(shg + col + 1, acc1);
            }
        }
    }
    __syncthreads();   // S5

    // ---- tail (warp 0): 2x (V@Wo + LN) + MLP ----
    if (warp == 0) {
        float* shg  = (float*)(sm + B_HG);
        float* sVec = (float*)(sm + B_VEC);
        float hgk = (lane < 20) ? shg[lane] * (1.f / NPG) : 0.f;

        {
            const float4* xr = (const float4*)(self_feat + (size_t)g * 200);
            const float4* wr = (const float4*)(Wv2 + lane * 200);
            float acc = 0.f;
            #pragma unroll 5
            for (int p = 0; p < 50; p++) {
                float4 a = wr[p], b = xr[p];
                acc += a.x * b.x + a.y * b.y + a.z * b.z + a.w * b.w;
            }
            sVec[lane] = acc;
        }
        __syncwarp();
        float y = 0.f;
        if (lane < 20) {
            const float* wo = Wo2 + lane * 32;
            float z = 0.f;
            #pragma unroll
            for (int j = 0; j < 32; j++) z += wo[j] * sVec[j];
            y = hgk + z;
        }
        float s = y;
        #pragma unroll
        for (int o = 16; o; o >>= 1) s += __shfl_xor_sync(0xffffffffu, s, o);
        float mu = s * (1.f / 20.f);
        float dd = (lane < 20) ? (y - mu) : 0.f;
        float vv = dd * dd;
        #pragma unroll
        for (int o = 16; o; o >>= 1) vv += __shfl_xor_sync(0xffffffffu, vv, o);
        float hg1 = 0.f;
        if (lane < 20)
            hg1 = dd * rsqrtf(vv * (1.f / 20.f) + 1e-5f) * g2[lane] + be2[lane];

        __syncwarp();
        {
            const float4* xr = (const float4*)(x3d + (size_t)g * 100);
            const float4* wr = (const float4*)(Wv3 + lane * 100);
            float acc = 0.f;
            #pragma unroll 5
            for (int p = 0; p < 25; p++) {
                float4 a = wr[p], b = xr[p];
                acc += a.x * b.x + a.y * b.y + a.z * b.z + a.w * b.w;
            }
            sVec[lane] = acc;
        }
        __syncwarp();
        float y2 = 0.f;
        if (lane < 20) {
            const float* wo = Wo3 + lane * 32;
            float z = 0.f;
            #pragma unroll
            for (int j = 0; j < 32; j++) z += wo[j] * sVec[j];
            y2 = hg1 + z;
        }
        float s2 = y2;
        #pragma unroll
        for (int o = 16; o; o >>= 1) s2 += __shfl_xor_sync(0xffffffffu, s2, o);
        float mu2 = s2 * (1.f / 20.f);
        float d2 = (lane < 20) ? (y2 - mu2) : 0.f;
        float v2s = d2 * d2;
        #pragma unroll
        for (int o = 16; o; o >>= 1) v2s += __shfl_xor_sync(0xffffffffu, v2s, o);
        float hg2 = 0.f;
        if (lane < 20)
            hg2 = d2 * rsqrtf(v2s * (1.f / 20.f) + 1e-5f) * g3[lane] + be3[lane];

        __syncwarp();
        if (lane < 20) sVec[lane] = hg2;
        __syncwarp();

        float f = 0.f;
        if (lane < 10) {
            const float* wf = Wf1 + lane * 20;
            float a = bf1[lane];
            #pragma unroll
            for (int k = 0; k < 20; k++) a += wf[k] * sVec[k];
            f = fmaxf(a, 0.f) * Wf2[lane];
        }
        #pragma unroll
        for (int o = 16; o; o >>= 1) f += __shfl_xor_sync(0xffffffffu, f, o);
        if (lane == 0) out[g] = f + bf2[0];
    }
}

// ============================ launch ============================
extern "C" void kernel_launch(void* const* d_in, const int* in_sizes, int n_in,
                              void* d_out, int out_size) {
    const float* feat      = (const float*)d_in[0];
    const int*   edge_src  = (const int*)  d_in[1];
    // d_in[2] = edge_dst: repeat(arange(N), DEG) by construction — implicit
    const float* self_feat = (const float*)d_in[3];
    const float* x3d       = (const float*)d_in[4];
    const float* W1  = (const float*)d_in[5];
    const float* b1  = (const float*)d_in[6];
    const float* W2  = (const float*)d_in[7];
    const float* b2  = (const float*)d_in[8];
    const float* Wv2 = (const float*)d_in[11];
    const float* Wo2 = (const float*)d_in[12];
    const float* g2  = (const float*)d_in[13];
    const float* be2 = (const float*)d_in[14];
    const float* Wv3 = (const float*)d_in[17];
    const float* Wo3 = (const float*)d_in[18];
    const float* g3  = (const float*)d_in[19];
    const float* be3 = (const float*)d_in[20];
    const float* Wf1 = (const float*)d_in[21];
    const float* bf1 = (const float*)d_in[22];
    const float* Wf2 = (const float*)d_in[23];
    const float* bf2 = (const float*)d_in[24];

    cudaFuncSetAttribute(gemm1_kernel,
                         cudaFuncAttributeMaxDynamicSharedMemorySize,
                         (int)K1_SMEM);
    gemm1_kernel<<<NNODES / 128, BLK, K1_SMEM>>>(feat, W1);

    cudaFuncSetAttribute(gnn_rest_kernel,
                         cudaFuncAttributeMaxDynamicSharedMemorySize,
                         K2_BYTES);
    gnn_rest_kernel<<<NGRAPH, BLK, K2_BYTES>>>(
        edge_src, self_feat, x3d,
        b1, W2, b2,
        Wv2, Wo2, g2, be2,
        Wv3, Wo3, g3, be3,
        Wf1, bf1, Wf2, bf2,
        (float*)d_out);
}